// round 3
// baseline (speedup 1.0000x reference)
#include <cuda_runtime.h>
#include <stdint.h>

// decoder_11218454577221
// score[e,c] = 1 / ((dist[e] - m[c])^2 + b)
// dist[e]    = sum_h softmax(w)_h * || h[dst,h,:] - h[src,h,:] ||_2
//
// Round 3: 8-lanes-per-edge, 4 edges per warp-iteration.
//  - gather: lane (sub*8+hl) loads float4 hl of each 128B chunk j of both rows
//    -> every LDG.128 is 4x128B fully-coalesced (4 wf), 8 wf/edge total.
//  - reduction: shuffle-packing ("exchange" trick): 3 shfls give each lane a
//    complete per-head sum (1 sqrt/lane), 3 more shfls give dist on all lanes.
//  - store: lane hl writes clusters [4hl,4hl+3] as float4 -> 512B contiguous.
// Wavefront budget: 8 gather + 1 store + 1.5 shfl + 0.25 LDS = 10.75/edge.

#define EPSF 1e-4f

__device__ float g_wsm[8];                    // softmax(w)
__device__ __align__(16) float g_m[32];       // relu(cumsum(|r+eps|+eps))
__device__ float g_b;
__device__ int   g_is64;

// ---------------------------------------------------------------------------
__global__ void prep_kernel(const float* __restrict__ w,
                            const float* __restrict__ r,
                            const float* __restrict__ b,
                            const void*  __restrict__ src,
                            const void*  __restrict__ dst,
                            int E)
{
    float wmax = w[0];
#pragma unroll
    for (int i = 1; i < 8; i++) wmax = fmaxf(wmax, w[i]);
    float ex[8];
    float s = 0.0f;
#pragma unroll
    for (int i = 0; i < 8; i++) { ex[i] = expf(w[i] - wmax); s += ex[i]; }
    float inv = 1.0f / s;
#pragma unroll
    for (int i = 0; i < 8; i++) g_wsm[i] = ex[i] * inv;

    float cum = 0.0f;
    for (int c = 0; c < 32; c++) {
        cum += fabsf(r[c] + EPSF) + EPSF;
        g_m[c] = fmaxf(cum, 0.0f);
    }
    g_b = b[0];

    // int64 vs int32: true int64 indices (< 2^31) have all-zero odd words.
    const int* s32 = (const int*)src;
    const int* d32 = (const int*)dst;
    int n = (E < 16) ? E : 16;
    int all0 = 1;
    for (int k = 0; k < n; k++) {
        if (s32[2 * k + 1] != 0) all0 = 0;
        if (d32[2 * k + 1] != 0) all0 = 0;
    }
    g_is64 = all0;
}

__device__ __forceinline__ float sq4(float4 a, float4 c)
{
    float dx = a.x - c.x, dy = a.y - c.y, dz = a.z - c.z, dw = a.w - c.w;
    float ss = dx * dx;
    ss = fmaf(dy, dy, ss);
    ss = fmaf(dz, dz, ss);
    ss = fmaf(dw, dw, ss);
    return ss;
}

// ---------------------------------------------------------------------------
__global__ __launch_bounds__(256)
void edge_kernel(const char* __restrict__ hbase,
                 const void* __restrict__ src,
                 const void* __restrict__ dst,
                 char* __restrict__ outbase,
                 int E)
{
    __shared__ int2 sidx[8][32];

    const int lane = threadIdx.x & 31;
    const int wIdx = threadIdx.x >> 5;
    const int warp = (blockIdx.x * blockDim.x + threadIdx.x) >> 5;
    const int base = warp << 5;
    if (base >= E) return;

    // stage this warp's 32 (src,dst) pairs
    {
        const int my_e = base + lane;
        const int e_cl = (my_e < E) ? my_e : (E - 1);
        int sv, dv;
        if (g_is64) {
            sv = (int)((const long long*)src)[e_cl];
            dv = (int)((const long long*)dst)[e_cl];
        } else {
            sv = ((const int*)src)[e_cl];
            dv = ((const int*)dst)[e_cl];
        }
        sidx[wIdx][lane] = make_int2(sv, dv);
    }
    __syncwarp();

    const int sub = lane >> 3;                       // edge within quad
    const int hl  = lane & 7;
    // after the packed reduction, this lane holds head sum P_{hl&3} of
    // the (hl<4 ? even : odd) head set -> head index:
    const int head = 2 * (hl & 3) + ((hl >> 2) & 1);
    const float wh = g_wsm[head];
    const float4 m4 = *(const float4*)&g_m[4 * hl];  // clusters 4hl..4hl+3
    const float bv = g_b;
    const unsigned hloff = (unsigned)hl * 16u;
    const bool p1 = (hl & 1);
    const bool p2b = (hl & 2);

    const bool full = (base + 32 <= E);

    for (int i = 0; i < 8; i++) {
        const int e = base + 4 * i + sub;
        const int2 pr = sidx[wIdx][4 * i + sub];

        const char* rs = hbase + (unsigned)pr.x * 512u + hloff;
        const char* rd = hbase + (unsigned)pr.y * 512u + hloff;

        // batched gather: 8 LDG.128, each 4x128B coalesced
        float4 a0 = *(const float4*)(rs);
        float4 a1 = *(const float4*)(rs + 128);
        float4 a2 = *(const float4*)(rs + 256);
        float4 a3 = *(const float4*)(rs + 384);
        float4 c0 = *(const float4*)(rd);
        float4 c1 = *(const float4*)(rd + 128);
        float4 c2 = *(const float4*)(rd + 256);
        float4 c3 = *(const float4*)(rd + 384);

        // chunk j holds heads {2j, 2j+1}; this lane's segment -> head 2j+(hl>=4)
        float q0 = sq4(a0, c0);
        float q1 = sq4(a1, c1);
        float q2 = sq4(a2, c2);
        float q3 = sq4(a3, c3);

        // packed butterfly: 3 shfls -> lane hl&3 holds complete head-sum P
        float gA = p1 ? q0 : q1;
        float A = (p1 ? q1 : q0) + __shfl_xor_sync(0xffffffffu, gA, 1);
        float gB = p1 ? q2 : q3;
        float B = (p1 ? q3 : q2) + __shfl_xor_sync(0xffffffffu, gB, 1);
        float gP = p2b ? A : B;
        float P = (p2b ? B : A) + __shfl_xor_sync(0xffffffffu, gP, 2);

        // one sqrt per lane; sum the 8 weighted head norms across the octet
        float v = sqrtf(P) * wh;
        v += __shfl_xor_sync(0xffffffffu, v, 1);
        v += __shfl_xor_sync(0xffffffffu, v, 2);
        v += __shfl_xor_sync(0xffffffffu, v, 4);
        // v == dist[e] on all 8 lanes of this edge's octet

        float t0 = v - m4.x;
        float t1 = v - m4.y;
        float t2 = v - m4.z;
        float t3 = v - m4.w;
        float4 o;
        o.x = __fdividef(1.0f, fmaf(t0, t0, bv));
        o.y = __fdividef(1.0f, fmaf(t1, t1, bv));
        o.z = __fdividef(1.0f, fmaf(t2, t2, bv));
        o.w = __fdividef(1.0f, fmaf(t3, t3, bv));

        if (full || e < E) {
            *(float4*)(outbase + (unsigned)e * 128u + hloff) = o;
        }
    }
}

// ---------------------------------------------------------------------------
// inputs: 0:h f32[N,H,D]  1:w f32[H]  2:r f32[1,C]  3:b f32[1]
//         4:src int[E]    5:dst int[E]      out: f32[E,C]
// ---------------------------------------------------------------------------
extern "C" void kernel_launch(void* const* d_in, const int* in_sizes, int n_in,
                              void* d_out, int out_size)
{
    const float* h = (const float*)d_in[0];
    const float* w = (const float*)d_in[1];
    const float* r = (const float*)d_in[2];
    const float* b = (const float*)d_in[3];
    const void*  src = d_in[4];
    const void*  dst = d_in[5];
    const int E = in_sizes[4];

    prep_kernel<<<1, 1>>>(w, r, b, src, dst, E);

    const int warps  = (E + 31) / 32;
    const int blocks = (warps + 7) / 8;
    edge_kernel<<<blocks, 256>>>((const char*)h, src, dst, (char*)d_out, E);
}

// round 5
// speedup vs baseline: 1.0333x; 1.0333x over previous
#include <cuda_runtime.h>
#include <stdint.h>

// decoder_11218454577221
// score[e,c] = 1 / ((dist[e] - m[c])^2 + b)
// dist[e]    = sum_h softmax(w)_h * || h[dst,h,:] - h[src,h,:] ||_2
//
// Round 4: R3 structure (8 lanes/edge, 10.75 wf/edge) + cache-policy fix:
//  - output stores use .cs (evict-first streaming) so the 256MB out-stream
//    stops evicting the 51MB L2-resident h table (measured ~120MB of h
//    re-fetch DRAM traffic in R2/R3);
//  - index loads use .cs (read-once).

#define EPSF 1e-4f

__device__ float g_wsm[8];                    // softmax(w)
__device__ __align__(16) float g_m[32];       // relu(cumsum(|r+eps|+eps))
__device__ float g_b;
__device__ int   g_is64;

// ---------------------------------------------------------------------------
__global__ void prep_kernel(const float* __restrict__ w,
                            const float* __restrict__ r,
                            const float* __restrict__ b,
                            const void*  __restrict__ src,
                            const void*  __restrict__ dst,
                            int E)
{
    float wmax = w[0];
#pragma unroll
    for (int i = 1; i < 8; i++) wmax = fmaxf(wmax, w[i]);
    float ex[8];
    float s = 0.0f;
#pragma unroll
    for (int i = 0; i < 8; i++) { ex[i] = expf(w[i] - wmax); s += ex[i]; }
    float inv = 1.0f / s;
#pragma unroll
    for (int i = 0; i < 8; i++) g_wsm[i] = ex[i] * inv;

    float cum = 0.0f;
    for (int c = 0; c < 32; c++) {
        cum += fabsf(r[c] + EPSF) + EPSF;
        g_m[c] = fmaxf(cum, 0.0f);
    }
    g_b = b[0];

    // int64 vs int32: true int64 indices (< 2^31) have all-zero odd words.
    const int* s32 = (const int*)src;
    const int* d32 = (const int*)dst;
    int n = (E < 16) ? E : 16;
    int all0 = 1;
    for (int k = 0; k < n; k++) {
        if (s32[2 * k + 1] != 0) all0 = 0;
        if (d32[2 * k + 1] != 0) all0 = 0;
    }
    g_is64 = all0;
}

__device__ __forceinline__ float sq4(float4 a, float4 c)
{
    float dx = a.x - c.x, dy = a.y - c.y, dz = a.z - c.z, dw = a.w - c.w;
    float ss = dx * dx;
    ss = fmaf(dy, dy, ss);
    ss = fmaf(dz, dz, ss);
    ss = fmaf(dw, dw, ss);
    return ss;
}

// ---------------------------------------------------------------------------
__global__ __launch_bounds__(256)
void edge_kernel(const char* __restrict__ hbase,
                 const void* __restrict__ src,
                 const void* __restrict__ dst,
                 char* __restrict__ outbase,
                 int E)
{
    __shared__ int2 sidx[8][32];

    const int lane = threadIdx.x & 31;
    const int wIdx = threadIdx.x >> 5;
    const int warp = (blockIdx.x * blockDim.x + threadIdx.x) >> 5;
    const int base = warp << 5;
    if (base >= E) return;

    // stage this warp's 32 (src,dst) pairs (streaming loads: read-once)
    {
        const int my_e = base + lane;
        const int e_cl = (my_e < E) ? my_e : (E - 1);
        int sv, dv;
        if (g_is64) {
            sv = (int)__ldcs(&((const long long*)src)[e_cl]);
            dv = (int)__ldcs(&((const long long*)dst)[e_cl]);
        } else {
            sv = __ldcs(&((const int*)src)[e_cl]);
            dv = __ldcs(&((const int*)dst)[e_cl]);
        }
        sidx[wIdx][lane] = make_int2(sv, dv);
    }
    __syncwarp();

    const int sub = lane >> 3;                       // edge within quad
    const int hl  = lane & 7;
    const int head = 2 * (hl & 3) + ((hl >> 2) & 1);
    const float wh = g_wsm[head];
    const float4 m4 = *(const float4*)&g_m[4 * hl];  // clusters 4hl..4hl+3
    const float bv = g_b;
    const unsigned hloff = (unsigned)hl * 16u;
    const bool p1 = (hl & 1);
    const bool p2b = (hl & 2);

    const bool full = (base + 32 <= E);

    for (int i = 0; i < 8; i++) {
        const int e = base + 4 * i + sub;
        const int2 pr = sidx[wIdx][4 * i + sub];

        const char* rs = hbase + (unsigned)pr.x * 512u + hloff;
        const char* rd = hbase + (unsigned)pr.y * 512u + hloff;

        // batched gather: 8 LDG.128, each 4x128B coalesced (wants L2 residency)
        float4 a0 = *(const float4*)(rs);
        float4 a1 = *(const float4*)(rs + 128);
        float4 a2 = *(const float4*)(rs + 256);
        float4 a3 = *(const float4*)(rs + 384);
        float4 c0 = *(const float4*)(rd);
        float4 c1 = *(const float4*)(rd + 128);
        float4 c2 = *(const float4*)(rd + 256);
        float4 c3 = *(const float4*)(rd + 384);

        float q0 = sq4(a0, c0);
        float q1 = sq4(a1, c1);
        float q2 = sq4(a2, c2);
        float q3 = sq4(a3, c3);

        // packed butterfly: 3 shfls -> each lane holds one complete head-sum
        float gA = p1 ? q0 : q1;
        float A = (p1 ? q1 : q0) + __shfl_xor_sync(0xffffffffu, gA, 1);
        float gB = p1 ? q2 : q3;
        float B = (p1 ? q3 : q2) + __shfl_xor_sync(0xffffffffu, gB, 1);
        float gP = p2b ? A : B;
        float P = (p2b ? B : A) + __shfl_xor_sync(0xffffffffu, gP, 2);

        // one sqrt per lane; sum weighted head norms across the octet
        float v = sqrtf(P) * wh;
        v += __shfl_xor_sync(0xffffffffu, v, 1);
        v += __shfl_xor_sync(0xffffffffu, v, 2);
        v += __shfl_xor_sync(0xffffffffu, v, 4);
        // v == dist[e] on all 8 lanes of this edge's octet

        float t0 = v - m4.x;
        float t1 = v - m4.y;
        float t2 = v - m4.z;
        float t3 = v - m4.w;
        float4 o;
        o.x = __fdividef(1.0f, fmaf(t0, t0, bv));
        o.y = __fdividef(1.0f, fmaf(t1, t1, bv));
        o.z = __fdividef(1.0f, fmaf(t2, t2, bv));
        o.w = __fdividef(1.0f, fmaf(t3, t3, bv));

        if (full || e < E) {
            // evict-first streaming store: keep h resident in L2
            __stcs((float4*)(outbase + (unsigned)e * 128u + hloff), o);
        }
    }
}

// ---------------------------------------------------------------------------
// inputs: 0:h f32[N,H,D]  1:w f32[H]  2:r f32[1,C]  3:b f32[1]
//         4:src int[E]    5:dst int[E]      out: f32[E,C]
// ---------------------------------------------------------------------------
extern "C" void kernel_launch(void* const* d_in, const int* in_sizes, int n_in,
                              void* d_out, int out_size)
{
    const float* h = (const float*)d_in[0];
    const float* w = (const float*)d_in[1];
    const float* r = (const float*)d_in[2];
    const float* b = (const float*)d_in[3];
    const void*  src = d_in[4];
    const void*  dst = d_in[5];
    const int E = in_sizes[4];

    prep_kernel<<<1, 1>>>(w, r, b, src, dst, E);

    const int warps  = (E + 31) / 32;
    const int blocks = (warps + 7) / 8;
    edge_kernel<<<blocks, 256>>>((const char*)h, src, dst, (char*)d_out, E);
}